// round 1
// baseline (speedup 1.0000x reference)
#include <cuda_runtime.h>
#include <math.h>

#define HW 65536
#define IMG 256
#define CB 96
#define BATCH 4

// ---------------- device scratch ----------------
__device__ float g_mean[BATCH], g_istd[BATCH], g_stdv[BATCH];
__device__ float g_rescale[BATCH][CB], g_rebias[BATCH][CB];
__device__ float g_partial[BATCH][192][2];
__device__ float g_bias_tab[3][64][64];

__device__ float g_tla[(size_t)BATCH*CB*HW];
__device__ float g_tta[(size_t)BATCH*CB*HW];
__device__ float g_y  [(size_t)BATCH*CB*HW];
__device__ float g_qkv[(size_t)BATCH*3*CB*HW];
__device__ float g_co [(size_t)BATCH*CB*HW];
__device__ float g_attn[(size_t)BATCH*HW*CB];   // pixel-major [b][hw][c]
__device__ float g_x2 [(size_t)BATCH*CB*HW];
__device__ float g_hid[(size_t)BATCH*4*CB*HW];

__constant__ float c_EPS = 1e-5f;
#define SCALEV 0.17677669529663687f
#define LOGIT_MAXV 4.605170185988091f

// ---------------- f32x2 helpers ----------------
__device__ __forceinline__ unsigned long long pack2(float w){
  unsigned long long r; asm("mov.b64 %0, {%1, %1};" : "=l"(r) : "f"(w)); return r;
}
__device__ __forceinline__ unsigned long long f2u(float x, float y){
  unsigned long long r; asm("mov.b64 %0, {%1, %2};" : "=l"(r) : "f"(x), "f"(y)); return r;
}
__device__ __forceinline__ float2 u2f(unsigned long long v){
  float2 f; asm("mov.b64 {%0, %1}, %2;" : "=f"(f.x), "=f"(f.y) : "l"(v)); return f;
}
__device__ __forceinline__ void ffma2(unsigned long long &d, unsigned long long a, unsigned long long b){
  asm("fma.rn.f32x2 %0, %1, %2, %0;" : "+l"(d) : "l"(a), "l"(b));
}

// ---------------- K1: per-sample partial sums ----------------
__global__ void k_reduce_partial(const float* __restrict__ x){
  int b = blockIdx.y, blk = blockIdx.x, tid = threadIdx.x;
  const float4* xb = (const float4*)(x + (size_t)b*CB*HW);
  size_t base = (size_t)blk*8192;   // 192 blocks * 8192 float4 = 1572864 float4/sample
  float s=0.f, s2=0.f;
  for (int i=tid;i<8192;i+=256){
    float4 v = xb[base+i];
    s  += v.x+v.y+v.z+v.w;
    s2 += v.x*v.x+v.y*v.y+v.z*v.z+v.w*v.w;
  }
  __shared__ float rs[256], rq[256];
  rs[tid]=s; rq[tid]=s2; __syncthreads();
  for (int st=128;st>0;st>>=1){
    if (tid<st){ rs[tid]+=rs[tid+st]; rq[tid]+=rq[tid+st]; }
    __syncthreads();
  }
  if (tid==0){ g_partial[b][blk][0]=rs[0]; g_partial[b][blk][1]=rq[0]; }
}

// ---------------- K2: finalize mean/std + rescale/rebias ----------------
__global__ void k_finalize(const float* __restrict__ m1w, const float* __restrict__ m1b,
                           const float* __restrict__ m2w, const float* __restrict__ m2b){
  int b = blockIdx.x, tid = threadIdx.x;
  __shared__ float rs[256], rq[256];
  rs[tid] = (tid<192)? g_partial[b][tid][0] : 0.f;
  rq[tid] = (tid<192)? g_partial[b][tid][1] : 0.f;
  __syncthreads();
  for (int st=128;st>0;st>>=1){
    if (tid<st){ rs[tid]+=rs[tid+st]; rq[tid]+=rq[tid+st]; }
    __syncthreads();
  }
  __shared__ float sh_mean, sh_std;
  if (tid==0){
    float M = (float)((size_t)CB*HW);
    float mean = rs[0]/M;
    float var  = rq[0]/M - mean*mean;
    float sd   = sqrtf(var + c_EPS);
    g_mean[b]=mean; g_stdv[b]=sd; g_istd[b]=1.f/sd;
    sh_mean=mean; sh_std=sd;
  }
  __syncthreads();
  if (tid<CB){
    g_rescale[b][tid] = sh_std *m1w[tid] + m1b[tid];
    g_rebias [b][tid] = sh_mean*m2w[tid] + m2b[tid];
  }
}

// ---------------- K3: relative-position bias table ----------------
__global__ void k_bias(const float* __restrict__ w1, const float* __restrict__ b1,
                       const float* __restrict__ w2, const float* __restrict__ b2){
  int n = blockIdx.x, m = threadIdx.x;
  float di = (float)((n>>3) - (m>>3));
  float dj = (float)((n&7) - (m&7));
  float a0l = log1pf(fabsf(di)); float r0 = di<0.f ? -a0l : (di>0.f ? a0l : 0.f);
  float a1l = log1pf(fabsf(dj)); float r1 = dj<0.f ? -a1l : (dj>0.f ? a1l : 0.f);
  float a0=0.f,a1=0.f,a2=0.f;
  for (int k=0;k<256;k++){
    float h = fmaxf(r0*w1[2*k]+r1*w1[2*k+1]+b1[k], 0.f);
    a0 += h*w2[k]; a1 += h*w2[256+k]; a2 += h*w2[512+k];
  }
  g_bias_tab[0][n][m]=a0+b2[0];
  g_bias_tab[1][n][m]=a1+b2[1];
  g_bias_tab[2][n][m]=a2+b2[2];
}

// ---------------- K4: AGN branch stage-1 (two 3x3 dwconv + relu) ----------------
__global__ void k_branch1(const float* __restrict__ x,
    const float* __restrict__ la1w, const float* __restrict__ la1b,
    const float* __restrict__ ta1w, const float* __restrict__ ta1b){
  int bc = blockIdx.z; int b = bc/CB, c = bc - b*CB;
  const float* xb = x + (size_t)bc*HW;
  float mean = g_mean[b], istd = g_istd[b];
  __shared__ float tile[10][34];
  int x0 = blockIdx.x*32, y0 = blockIdx.y*8;
  int tid = threadIdx.y*32 + threadIdx.x;
  for (int i=tid; i<340; i+=256){
    int ry = i/34, rx = i-ry*34;
    int gy = y0+ry-1, gx = x0+rx-1;
    float v = 0.f;
    if ((unsigned)gy<256u && (unsigned)gx<256u) v = (xb[gy*256+gx]-mean)*istd;
    tile[ry][rx] = v;
  }
  __syncthreads();
  float wl[9], wt[9];
  #pragma unroll
  for (int k=0;k<9;k++){ wl[k]=la1w[c*9+k]; wt[k]=ta1w[c*9+k]; }
  int ty=threadIdx.y, tx=threadIdx.x;
  float al = la1b[c], at = ta1b[c];
  #pragma unroll
  for (int ky=0;ky<3;ky++)
    #pragma unroll
    for (int kx=0;kx<3;kx++){
      float v = tile[ty+ky][tx+kx];
      al += v*wl[ky*3+kx]; at += v*wt[ky*3+kx];
    }
  size_t o = (size_t)bc*HW + (size_t)(y0+ty)*256 + x0+tx;
  g_tla[o] = fmaxf(al,0.f);
  g_tta[o] = fmaxf(at,0.f);
}

// ---------------- K5: AGN final (two 3x3 dwconv + affine) ----------------
__global__ void k_agn_final(const float* __restrict__ x,
    const float* __restrict__ agnw, const float* __restrict__ agnb,
    const float* __restrict__ la2w, const float* __restrict__ la2b,
    const float* __restrict__ ta2w, const float* __restrict__ ta2b){
  int bc=blockIdx.z; int b=bc/CB, c=bc-b*CB;
  __shared__ float tl[10][34], tt[10][34];
  int x0=blockIdx.x*32, y0=blockIdx.y*8;
  int tid = threadIdx.y*32+threadIdx.x;
  const float* pla = g_tla + (size_t)bc*HW;
  const float* pta = g_tta + (size_t)bc*HW;
  for (int i=tid;i<340;i+=256){
    int ry=i/34, rx=i-ry*34;
    int gy=y0+ry-1, gx=x0+rx-1;
    bool in = (unsigned)gy<256u && (unsigned)gx<256u;
    int gi = gy*256+gx;
    tl[ry][rx] = in ? pla[gi] : 0.f;
    tt[ry][rx] = in ? pta[gi] : 0.f;
  }
  __syncthreads();
  float wl[9], wt[9];
  #pragma unroll
  for (int k=0;k<9;k++){ wl[k]=la2w[c*9+k]; wt[k]=ta2w[c*9+k]; }
  int ty=threadIdx.y, tx=threadIdx.x;
  float acc = la2b[c] + ta2b[c];
  #pragma unroll
  for (int ky=0;ky<3;ky++)
    #pragma unroll
    for (int kx=0;kx<3;kx++){
      acc += tl[ty+ky][tx+kx]*wl[ky*3+kx] + tt[ty+ky][tx+kx]*wt[ky*3+kx];
    }
  float mean=g_mean[b], istd=g_istd[b];
  size_t o = (size_t)bc*HW + (size_t)(y0+ty)*256 + x0+tx;
  float xn = (x[o]-mean)*istd;
  g_y[o] = xn*(agnw[c]*g_rescale[b][c]) + (agnb[c]+g_rebias[b][c]) + acc;
}

// ---------------- K6: 5x5 reflect-padded dwconv on Q ----------------
__global__ void k_co5(const float* __restrict__ dww, const float* __restrict__ dwb){
  int bc=blockIdx.z; int b=bc/CB, c=bc-b*CB;
  const float* Q = g_qkv + ((size_t)b*3*CB + c)*HW;
  __shared__ float tile[12][36];
  int x0=blockIdx.x*32, y0=blockIdx.y*8;
  int tid=threadIdx.y*32+threadIdx.x;
  for (int i=tid;i<432;i+=256){
    int ry=i/36, rx=i-ry*36;
    int gy=y0+ry-2, gx=x0+rx-2;
    gy = gy<0 ? -gy : (gy>255 ? 510-gy : gy);
    gx = gx<0 ? -gx : (gx>255 ? 510-gx : gx);
    tile[ry][rx] = Q[gy*256+gx];
  }
  __syncthreads();
  float w[25];
  #pragma unroll
  for (int k=0;k<25;k++) w[k]=dww[c*25+k];
  float acc = dwb[c];
  #pragma unroll
  for (int ky=0;ky<5;ky++)
    #pragma unroll
    for (int kx=0;kx<5;kx++)
      acc += tile[threadIdx.y+ky][threadIdx.x+kx]*w[ky*5+kx];
  g_co[(size_t)bc*HW + (size_t)(y0+threadIdx.y)*256 + x0+threadIdx.x] = acc;
}

// ---------------- channel-major GEMM: out[b][o][px] = W @ act + bias ----------------
// EPI: 0 none, 1 relu, 2 add residual (same layout as out)
template<int EPI>
__global__ void __launch_bounds__(256,2) k_gemm_cm(
    const float* __restrict__ act, size_t actBS,
    const float* __restrict__ W, const float* __restrict__ bias,
    float* __restrict__ out, size_t outBS, int chanBase,
    int Cin, const float* __restrict__ resid)
{
  extern __shared__ float smem[];
  float* sA = smem;            // [96][128]
  float* sW = smem + 96*128;   // [96][96]
  const int tid = threadIdx.x;
  const int tx = tid & 31, ty = tid >> 5;
  const int b = blockIdx.z;
  const int px0 = blockIdx.x * 128;
  const int wrow0 = blockIdx.y * 96;
  const float* actb = act + (size_t)b*actBS;

  unsigned long long acc[12][2];
  #pragma unroll
  for (int i=0;i<12;i++){ acc[i][0]=0ull; acc[i][1]=0ull; }

  for (int k0=0;k0<Cin;k0+=96){
    #pragma unroll
    for (int j=0;j<12;j++){
      int i = tid + 256*j;
      int c = i >> 5, p4 = i & 31;
      ((float4*)sA)[c*32 + p4] = *(const float4*)(actb + (size_t)(k0+c)*HW + px0 + p4*4);
    }
    #pragma unroll
    for (int j=0;j<36;j++){
      int i = tid + 256*j;
      int r = i/96, cc = i - r*96;
      sW[r*96+cc] = W[(size_t)(wrow0+r)*Cin + k0 + cc];
    }
    __syncthreads();
    #pragma unroll 4
    for (int c=0;c<96;c++){
      float4 a = ((const float4*)sA)[c*32 + tx];
      unsigned long long a0 = f2u(a.x,a.y), a1 = f2u(a.z,a.w);
      #pragma unroll
      for (int i=0;i<12;i++){
        unsigned long long w2 = pack2(sW[(ty+8*i)*96 + c]);
        ffma2(acc[i][0], w2, a0);
        ffma2(acc[i][1], w2, a1);
      }
    }
    __syncthreads();
  }
  #pragma unroll
  for (int i=0;i<12;i++){
    int olocal = wrow0 + ty + 8*i;
    float bv = bias[olocal];
    float2 p0 = u2f(acc[i][0]), p1 = u2f(acc[i][1]);
    float4 v = make_float4(p0.x+bv, p0.y+bv, p1.x+bv, p1.y+bv);
    size_t off = (size_t)b*outBS + (size_t)(chanBase+olocal)*HW + px0 + tx*4;
    if (EPI==1){
      v.x=fmaxf(v.x,0.f); v.y=fmaxf(v.y,0.f); v.z=fmaxf(v.z,0.f); v.w=fmaxf(v.w,0.f);
    } else if (EPI==2){
      float4 r = *(const float4*)(resid + off);
      v.x+=r.x; v.y+=r.y; v.z+=r.z; v.w+=r.w;
    }
    *(float4*)(out + off) = v;
  }
}

// ---------------- proj GEMM: pixel-major act, epilogue x + a*rescale + rebias ----------------
__global__ void __launch_bounds__(256,2) k_gemm_proj(
    const float* __restrict__ actPM,
    const float* __restrict__ W, const float* __restrict__ bias,
    const float* __restrict__ xin, float* __restrict__ out)
{
  extern __shared__ float smem[];
  float* sA = smem;             // [96][132] (transposed, padded)
  float* sW = smem + 96*132;    // [96][96]
  const int tid=threadIdx.x, tx=tid&31, ty=tid>>5;
  const int b = blockIdx.z, px0 = blockIdx.x*128;
  const float* src = actPM + ((size_t)b*HW + px0)*96;
  #pragma unroll
  for (int j=0;j<12;j++){
    int i4 = tid + 256*j;            // 3072 float4 = 12288 floats
    float4 v = ((const float4*)src)[i4];
    int f = i4*4; int px = f/96; int c0 = f - px*96;
    sA[(c0+0)*132+px]=v.x; sA[(c0+1)*132+px]=v.y;
    sA[(c0+2)*132+px]=v.z; sA[(c0+3)*132+px]=v.w;
  }
  #pragma unroll
  for (int j=0;j<36;j++){
    int i = tid + 256*j;
    sW[i] = W[i];
  }
  __syncthreads();
  unsigned long long acc[12][2];
  #pragma unroll
  for (int i=0;i<12;i++){ acc[i][0]=0ull; acc[i][1]=0ull; }
  #pragma unroll 4
  for (int c=0;c<96;c++){
    float4 a = *(const float4*)(sA + c*132 + tx*4);
    unsigned long long a0 = f2u(a.x,a.y), a1 = f2u(a.z,a.w);
    #pragma unroll
    for (int i=0;i<12;i++){
      unsigned long long w2 = pack2(sW[(ty+8*i)*96 + c]);
      ffma2(acc[i][0], w2, a0);
      ffma2(acc[i][1], w2, a1);
    }
  }
  #pragma unroll
  for (int i=0;i<12;i++){
    int o = ty + 8*i;
    float bv = bias[o];
    float rs = g_rescale[b][o], rb = g_rebias[b][o];
    float2 p0 = u2f(acc[i][0]), p1 = u2f(acc[i][1]);
    size_t off = ((size_t)b*CB + o)*HW + px0 + tx*4;
    float4 xi = *(const float4*)(xin + off);
    float4 v = make_float4(
      xi.x + (p0.x+bv)*rs + rb,
      xi.y + (p0.y+bv)*rs + rb,
      xi.z + (p1.x+bv)*rs + rb,
      xi.w + (p1.y+bv)*rs + rb);
    *(float4*)(out + off) = v;
  }
}

// ---------------- attention: one (window, head) per 64-thread block ----------------
__global__ void __launch_bounds__(64) k_attn(const float* __restrict__ lsp){
  int widx=blockIdx.x, h=blockIdx.y;
  int b=widx>>10, rem=widx&1023;
  int r0=(rem>>5)*8, c0=(rem&31)*8;
  int t=threadIdx.x;
  __shared__ float sK[32][64], sV[32][64];
  float ls = __expf(fminf(lsp[0], LOGIT_MAXV));
  size_t baseK = ((size_t)b*3*CB +   CB + h*32)*HW;
  size_t baseV = ((size_t)b*3*CB + 2*CB + h*32)*HW;
  for (int i=t;i<2048;i+=64){
    int d=i>>6, tt=i&63;
    int hw = (r0+(tt>>3))*256 + c0 + (tt&7);
    sK[d][tt] = g_qkv[baseK + (size_t)d*HW + hw]*SCALEV;
    sV[d][tt] = g_qkv[baseV + (size_t)d*HW + hw];
  }
  int hw_t = (r0+(t>>3))*256 + c0 + (t&7);
  float q[32];
  size_t baseQ = ((size_t)b*CB + h*32)*HW;
  #pragma unroll
  for (int d=0;d<32;d++) q[d] = g_co[baseQ + (size_t)d*HW + hw_t];
  __syncthreads();
  float l[64];
  #pragma unroll
  for (int m=0;m<64;m++){
    float s=0.f;
    #pragma unroll
    for (int d=0;d<32;d++) s += q[d]*sK[d][m];
    l[m] = s*ls + g_bias_tab[h][t][m];
  }
  float mx=l[0];
  #pragma unroll
  for (int m=1;m<64;m++) mx = fmaxf(mx,l[m]);
  float sum=0.f;
  #pragma unroll
  for (int m=0;m<64;m++){ float e=__expf(l[m]-mx); l[m]=e; sum+=e; }
  float inv = 1.f/sum;
  float o[32];
  #pragma unroll
  for (int d=0;d<32;d++) o[d]=0.f;
  #pragma unroll
  for (int m=0;m<64;m++){
    float p=l[m];
    #pragma unroll
    for (int d=0;d<32;d++) o[d] += p*sV[d][m];
  }
  float* dst = g_attn + ((size_t)b*HW + hw_t)*96 + h*32;
  #pragma unroll
  for (int d=0;d<32;d+=4){
    float4 v = make_float4(o[d]*inv, o[d+1]*inv, o[d+2]*inv, o[d+3]*inv);
    *(float4*)(dst+d) = v;
  }
}

// ---------------- host launch ----------------
extern "C" void kernel_launch(void* const* d_in, const int* in_sizes, int n_in,
                              void* d_out, int out_size){
  const float* x       = (const float*)d_in[0];
  const float* agn_w   = (const float*)d_in[1];
  const float* agn_b   = (const float*)d_in[2];
  const float* meta1_w = (const float*)d_in[3];
  const float* meta1_b = (const float*)d_in[4];
  const float* meta2_w = (const float*)d_in[5];
  const float* meta2_b = (const float*)d_in[6];
  const float* la1_w   = (const float*)d_in[7];
  const float* la1_b   = (const float*)d_in[8];
  const float* la2_w   = (const float*)d_in[9];
  const float* la2_b   = (const float*)d_in[10];
  const float* ta1_w   = (const float*)d_in[11];
  const float* ta1_b   = (const float*)d_in[12];
  const float* ta2_w   = (const float*)d_in[13];
  const float* ta2_b   = (const float*)d_in[14];
  const float* q_w     = (const float*)d_in[15];
  const float* q_b     = (const float*)d_in[16];
  const float* kv_w    = (const float*)d_in[17];
  const float* kv_b    = (const float*)d_in[18];
  const float* dw_w    = (const float*)d_in[19];
  const float* dw_b    = (const float*)d_in[20];
  const float* proj_w  = (const float*)d_in[21];
  const float* proj_b  = (const float*)d_in[22];
  const float* logit_s = (const float*)d_in[23];
  const float* rp_w1   = (const float*)d_in[24];
  const float* rp_b1   = (const float*)d_in[25];
  const float* rp_w2   = (const float*)d_in[26];
  const float* rp_b2   = (const float*)d_in[27];
  const float* m1_w    = (const float*)d_in[28];
  const float* m1_b    = (const float*)d_in[29];
  const float* m2_w    = (const float*)d_in[30];
  const float* m2_b    = (const float*)d_in[31];
  float* out = (float*)d_out;

  const int SM_CM = (96*128 + 96*96)*4;   // 86016
  const int SM_PM = (96*132 + 96*96)*4;   // 87552
  cudaFuncSetAttribute(k_gemm_cm<0>, cudaFuncAttributeMaxDynamicSharedMemorySize, SM_CM);
  cudaFuncSetAttribute(k_gemm_cm<1>, cudaFuncAttributeMaxDynamicSharedMemorySize, SM_CM);
  cudaFuncSetAttribute(k_gemm_cm<2>, cudaFuncAttributeMaxDynamicSharedMemorySize, SM_CM);
  cudaFuncSetAttribute(k_gemm_proj,  cudaFuncAttributeMaxDynamicSharedMemorySize, SM_PM);

  float *p_y, *p_qkv, *p_attn, *p_x2, *p_hid;
  cudaGetSymbolAddress((void**)&p_y,    g_y);
  cudaGetSymbolAddress((void**)&p_qkv,  g_qkv);
  cudaGetSymbolAddress((void**)&p_attn, g_attn);
  cudaGetSymbolAddress((void**)&p_x2,   g_x2);
  cudaGetSymbolAddress((void**)&p_hid,  g_hid);

  // 1. stats
  k_reduce_partial<<<dim3(192,BATCH), 256>>>(x);
  k_finalize<<<BATCH, 256>>>(meta1_w, meta1_b, meta2_w, meta2_b);
  k_bias<<<64, 64>>>(rp_w1, rp_b1, rp_w2, rp_b2);

  // 2. AGN
  dim3 cgrid(IMG/32, IMG/8, BATCH*CB), cblk(32, 8);
  k_branch1<<<cgrid, cblk>>>(x, la1_w, la1_b, ta1_w, ta1_b);
  k_agn_final<<<cgrid, cblk>>>(x, agn_w, agn_b, la2_w, la2_b, ta2_w, ta2_b);

  // 3. QKV projections (into g_qkv channels [0,96) and [96,288))
  k_gemm_cm<0><<<dim3(512,1,BATCH), 256, SM_CM>>>(p_y, (size_t)CB*HW, q_w,  q_b,
      p_qkv, (size_t)3*CB*HW, 0,  96, nullptr);
  k_gemm_cm<0><<<dim3(512,2,BATCH), 256, SM_CM>>>(p_y, (size_t)CB*HW, kv_w, kv_b,
      p_qkv, (size_t)3*CB*HW, 96, 96, nullptr);

  // 4. reflect 5x5 dwconv on Q -> co, then window attention
  k_co5<<<cgrid, cblk>>>(dw_w, dw_b);
  k_attn<<<dim3(4096,3), 64>>>(logit_s);

  // 5. proj + residual/rescale/rebias  -> g_x2
  k_gemm_proj<<<dim3(512,1,BATCH), 256, SM_PM>>>(p_attn, proj_w, proj_b, x, p_x2);

  // 6. MLP
  k_gemm_cm<1><<<dim3(512,4,BATCH), 256, SM_CM>>>(p_x2, (size_t)CB*HW, m1_w, m1_b,
      p_hid, (size_t)4*CB*HW, 0, 96, nullptr);
  k_gemm_cm<2><<<dim3(512,1,BATCH), 256, SM_CM>>>(p_hid, (size_t)4*CB*HW, m2_w, m2_b,
      out, (size_t)CB*HW, 0, 384, p_x2);
}

// round 3
// speedup vs baseline: 1.1538x; 1.1538x over previous
#include <cuda_runtime.h>
#include <math.h>

#define HW 65536
#define IMG 256
#define CB 96
#define BATCH 4

// ---------------- device scratch ----------------
__device__ float g_mean[BATCH], g_istd[BATCH];
__device__ float g_rescale[BATCH][CB], g_rebias[BATCH][CB];
__device__ float g_partial[BATCH][192][2];
__device__ float g_bias_tab[3][64][64];

__device__ float g_y  [(size_t)BATCH*CB*HW];
__device__ float g_qkv[(size_t)BATCH*3*CB*HW];
__device__ float g_co [(size_t)BATCH*CB*HW];
__device__ float g_attn[(size_t)BATCH*HW*CB];   // pixel-major [b][hw][c]
__device__ float g_x2 [(size_t)BATCH*CB*HW];
__device__ float g_hid[(size_t)BATCH*4*CB*HW];

#define SCALEV 0.17677669529663687f
#define LOGIT_MAXV 4.605170185988091f

// ---------------- f32x2 helpers ----------------
__device__ __forceinline__ unsigned long long pack2(float w){
  unsigned long long r; asm("mov.b64 %0, {%1, %1};" : "=l"(r) : "f"(w)); return r;
}
__device__ __forceinline__ float2 u2f(unsigned long long v){
  float2 f; asm("mov.b64 {%0, %1}, %2;" : "=f"(f.x), "=f"(f.y) : "l"(v)); return f;
}
__device__ __forceinline__ void ffma2(unsigned long long &d, unsigned long long a, unsigned long long b){
  asm("fma.rn.f32x2 %0, %1, %2, %0;" : "+l"(d) : "l"(a), "l"(b));
}

// ---------------- K1: per-sample partial sums ----------------
__global__ void k_reduce_partial(const float* __restrict__ x){
  int b = blockIdx.y, blk = blockIdx.x, tid = threadIdx.x;
  const float4* xb = (const float4*)(x + (size_t)b*CB*HW);
  size_t base = (size_t)blk*8192;
  float s=0.f, s2=0.f;
  for (int i=tid;i<8192;i+=256){
    float4 v = xb[base+i];
    s  += v.x+v.y+v.z+v.w;
    s2 += v.x*v.x+v.y*v.y+v.z*v.z+v.w*v.w;
  }
  __shared__ float rs[256], rq[256];
  rs[tid]=s; rq[tid]=s2; __syncthreads();
  for (int st=128;st>0;st>>=1){
    if (tid<st){ rs[tid]+=rs[tid+st]; rq[tid]+=rq[tid+st]; }
    __syncthreads();
  }
  if (tid==0){ g_partial[b][blk][0]=rs[0]; g_partial[b][blk][1]=rq[0]; }
}

// ---------------- K2: finalize mean/std + rescale/rebias ----------------
__global__ void k_finalize(const float* __restrict__ m1w, const float* __restrict__ m1b,
                           const float* __restrict__ m2w, const float* __restrict__ m2b){
  int b = blockIdx.x, tid = threadIdx.x;
  __shared__ float rs[256], rq[256];
  rs[tid] = (tid<192)? g_partial[b][tid][0] : 0.f;
  rq[tid] = (tid<192)? g_partial[b][tid][1] : 0.f;
  __syncthreads();
  for (int st=128;st>0;st>>=1){
    if (tid<st){ rs[tid]+=rs[tid+st]; rq[tid]+=rq[tid+st]; }
    __syncthreads();
  }
  __shared__ float sh_mean, sh_std;
  if (tid==0){
    float M = (float)((size_t)CB*HW);
    float mean = rs[0]/M;
    float var  = rq[0]/M - mean*mean;
    float sd   = sqrtf(var + 1e-5f);
    g_mean[b]=mean; g_istd[b]=1.f/sd;
    sh_mean=mean; sh_std=sd;
  }
  __syncthreads();
  if (tid<CB){
    g_rescale[b][tid] = sh_std *m1w[tid] + m1b[tid];
    g_rebias [b][tid] = sh_mean*m2w[tid] + m2b[tid];
  }
}

// ---------------- K3: relative-position bias table ----------------
__global__ void k_bias(const float* __restrict__ w1, const float* __restrict__ b1,
                       const float* __restrict__ w2, const float* __restrict__ b2){
  int n = blockIdx.x, m = threadIdx.x;
  float di = (float)((n>>3) - (m>>3));
  float dj = (float)((n&7) - (m&7));
  float a0l = log1pf(fabsf(di)); float r0 = di<0.f ? -a0l : (di>0.f ? a0l : 0.f);
  float a1l = log1pf(fabsf(dj)); float r1 = dj<0.f ? -a1l : (dj>0.f ? a1l : 0.f);
  float a0=0.f,a1=0.f,a2=0.f;
  for (int k=0;k<256;k++){
    float h = fmaxf(r0*w1[2*k]+r1*w1[2*k+1]+b1[k], 0.f);
    a0 += h*w2[k]; a1 += h*w2[256+k]; a2 += h*w2[512+k];
  }
  g_bias_tab[0][n][m]=a0+b2[0];
  g_bias_tab[1][n][m]=a1+b2[1];
  g_bias_tab[2][n][m]=a2+b2[2];
}

// ---------------- K4: fused AGN (two dwconv stages + affine) ----------------
__global__ void k_agn_fused(const float* __restrict__ x,
    const float* __restrict__ agnw, const float* __restrict__ agnb,
    const float* __restrict__ la1w, const float* __restrict__ la1b,
    const float* __restrict__ la2w, const float* __restrict__ la2b,
    const float* __restrict__ ta1w, const float* __restrict__ ta1b,
    const float* __restrict__ ta2w, const float* __restrict__ ta2b){
  int bc = blockIdx.z; int b = bc/CB, c = bc - b*CB;
  const float* xb = x + (size_t)bc*HW;
  float mean = g_mean[b], istd = g_istd[b];
  __shared__ float xt[12][36];
  __shared__ __align__(8) float2 tb[10][36];
  int x0 = blockIdx.x*32, y0 = blockIdx.y*8;
  int tid = threadIdx.y*32 + threadIdx.x;
  for (int i=tid; i<432; i+=256){
    int ry = i/36, rx = i-ry*36;
    int gy = y0+ry-2, gx = x0+rx-2;
    float v = 0.f;
    if ((unsigned)gy<256u && (unsigned)gx<256u) v = (xb[gy*256+gx]-mean)*istd;
    xt[ry][rx] = v;
  }
  float w1l[9], w1t[9], w2l[9], w2t[9];
  #pragma unroll
  for (int k=0;k<9;k++){
    w1l[k]=la1w[c*9+k]; w1t[k]=ta1w[c*9+k];
    w2l[k]=la2w[c*9+k]; w2t[k]=ta2w[c*9+k];
  }
  float b1l=la1b[c], b1t=ta1b[c];
  __syncthreads();
  // stage-1: 10x34 region of relu(dwconv3) for both branches
  for (int i=tid; i<340; i+=256){
    int ry = i/34, rx = i-ry*34;
    int gy = y0+ry-1, gx = x0+rx-1;
    float al=b1l, at=b1t;
    #pragma unroll
    for (int ky=0;ky<3;ky++)
      #pragma unroll
      for (int kx=0;kx<3;kx++){
        float v = xt[ry+ky][rx+kx];
        al += v*w1l[ky*3+kx]; at += v*w1t[ky*3+kx];
      }
    bool in = (unsigned)gy<256u && (unsigned)gx<256u;
    tb[ry][rx] = in ? make_float2(fmaxf(al,0.f), fmaxf(at,0.f)) : make_float2(0.f,0.f);
  }
  __syncthreads();
  int ty=threadIdx.y, tx=threadIdx.x;
  float acc = la2b[c] + ta2b[c];
  #pragma unroll
  for (int ky=0;ky<3;ky++)
    #pragma unroll
    for (int kx=0;kx<3;kx++){
      float2 v = tb[ty+ky][tx+kx];
      acc += v.x*w2l[ky*3+kx] + v.y*w2t[ky*3+kx];
    }
  float xn = xt[ty+2][tx+2];
  size_t o = (size_t)bc*HW + (size_t)(y0+ty)*256 + x0+tx;
  g_y[o] = xn*(agnw[c]*g_rescale[b][c]) + (agnb[c]+g_rebias[b][c]) + acc;
}

// ---------------- K6: 5x5 reflect-padded dwconv on Q ----------------
__global__ void k_co5(const float* __restrict__ dww, const float* __restrict__ dwb){
  int bc=blockIdx.z; int b=bc/CB, c=bc-b*CB;
  const float* Q = g_qkv + ((size_t)b*3*CB + c)*HW;
  __shared__ float tile[12][36];
  int x0=blockIdx.x*32, y0=blockIdx.y*8;
  int tid=threadIdx.y*32+threadIdx.x;
  for (int i=tid;i<432;i+=256){
    int ry=i/36, rx=i-ry*36;
    int gy=y0+ry-2, gx=x0+rx-2;
    gy = gy<0 ? -gy : (gy>255 ? 510-gy : gy);
    gx = gx<0 ? -gx : (gx>255 ? 510-gx : gx);
    tile[ry][rx] = Q[gy*256+gx];
  }
  __syncthreads();
  float w[25];
  #pragma unroll
  for (int k=0;k<25;k++) w[k]=dww[c*25+k];
  float acc = dwb[c];
  #pragma unroll
  for (int ky=0;ky<5;ky++)
    #pragma unroll
    for (int kx=0;kx<5;kx++)
      acc += tile[threadIdx.y+ky][threadIdx.x+kx]*w[ky*5+kx];
  g_co[(size_t)bc*HW + (size_t)(y0+threadIdx.y)*256 + x0+threadIdx.x] = acc;
}

// ---------------- GEMM core: out[o][px] = W @ act + bias ----------------
// smem: sA [96 c][128 px], sWt [96 c][pitch 100] transposed weights.
// 256 threads: tx 0..31 (4 px each), ty 0..7 (12 outputs each, f32x2-paired).
template<int EPI>
__device__ __forceinline__ void gemm_body(
    const float* __restrict__ actb, const float* __restrict__ W, int wrowW,
    const float* __restrict__ bias, int wrowB,
    float* __restrict__ outb, int chanBase, int Cin,
    const float* __restrict__ residb)
{
  extern __shared__ float smem[];
  float* sA  = smem;            // 96*128
  float* sWt = smem + 96*128;   // 96*100
  const int tid = threadIdx.x;
  const int tx = tid & 31, ty = tid >> 5;
  const int px0 = blockIdx.x * 128;

  unsigned long long acc[6][4];
  #pragma unroll
  for (int p=0;p<6;p++){ acc[p][0]=0ull; acc[p][1]=0ull; acc[p][2]=0ull; acc[p][3]=0ull; }

  for (int k0=0;k0<Cin;k0+=96){
    #pragma unroll
    for (int j=0;j<12;j++){
      int i = tid + 256*j;
      int cc = i >> 5, p4 = i & 31;
      ((float4*)sA)[cc*32 + p4] = *(const float4*)(actb + (size_t)(k0+cc)*HW + px0 + p4*4);
    }
    #pragma unroll
    for (int j=0;j<36;j++){
      int i = tid + 256*j;
      int r = i/96, cc = i - r*96;
      sWt[cc*100 + r] = W[(size_t)(wrowW+r)*Cin + k0 + cc];
    }
    __syncthreads();
    #pragma unroll 8
    for (int c=0;c<96;c++){
      float4 a = ((const float4*)sA)[c*32 + tx];
      unsigned long long a0=pack2(a.x), a1=pack2(a.y), a2=pack2(a.z), a3=pack2(a.w);
      const ulonglong2* wp = (const ulonglong2*)(sWt + c*100 + ty*12);
      ulonglong2 wA = wp[0], wB = wp[1], wC = wp[2];
      unsigned long long w[6] = {wA.x, wA.y, wB.x, wB.y, wC.x, wC.y};
      #pragma unroll
      for (int p=0;p<6;p++){
        ffma2(acc[p][0], w[p], a0);
        ffma2(acc[p][1], w[p], a1);
        ffma2(acc[p][2], w[p], a2);
        ffma2(acc[p][3], w[p], a3);
      }
    }
    __syncthreads();
  }
  #pragma unroll
  for (int p=0;p<6;p++){
    int o0 = ty*12 + 2*p, o1 = o0 + 1;
    float b0 = bias[wrowB+o0], b1 = bias[wrowB+o1];
    float2 r0=u2f(acc[p][0]), r1=u2f(acc[p][1]), r2=u2f(acc[p][2]), r3=u2f(acc[p][3]);
    float4 v0 = make_float4(r0.x+b0, r1.x+b0, r2.x+b0, r3.x+b0);
    float4 v1 = make_float4(r0.y+b1, r1.y+b1, r2.y+b1, r3.y+b1);
    size_t off0 = (size_t)(chanBase+o0)*HW + px0 + tx*4;
    size_t off1 = (size_t)(chanBase+o1)*HW + px0 + tx*4;
    if (EPI==1){
      v0.x=fmaxf(v0.x,0.f); v0.y=fmaxf(v0.y,0.f); v0.z=fmaxf(v0.z,0.f); v0.w=fmaxf(v0.w,0.f);
      v1.x=fmaxf(v1.x,0.f); v1.y=fmaxf(v1.y,0.f); v1.z=fmaxf(v1.z,0.f); v1.w=fmaxf(v1.w,0.f);
    } else if (EPI==2){
      float4 q0 = *(const float4*)(residb + off0);
      float4 q1 = *(const float4*)(residb + off1);
      v0.x+=q0.x; v0.y+=q0.y; v0.z+=q0.z; v0.w+=q0.w;
      v1.x+=q1.x; v1.y+=q1.y; v1.z+=q1.z; v1.w+=q1.w;
    }
    *(float4*)(outb + off0) = v0;
    *(float4*)(outb + off1) = v1;
  }
}

__global__ void __launch_bounds__(256,2) k_gemm_qkv(
    const float* __restrict__ act,
    const float* __restrict__ qW, const float* __restrict__ qb,
    const float* __restrict__ kvW, const float* __restrict__ kvb,
    float* __restrict__ out)
{
  int b = blockIdx.z, yb = blockIdx.y;
  const float* actb = act + (size_t)b*CB*HW;
  float* outb = out + (size_t)b*3*CB*HW;
  if (yb==0) gemm_body<0>(actb, qW, 0, qb, 0, outb, 0, 96, nullptr);
  else       gemm_body<0>(actb, kvW, (yb-1)*96, kvb, (yb-1)*96, outb, 96+(yb-1)*96, 96, nullptr);
}

__global__ void __launch_bounds__(256,2) k_gemm_m1(
    const float* __restrict__ act, const float* __restrict__ W,
    const float* __restrict__ bias, float* __restrict__ out)
{
  int b = blockIdx.z, g = blockIdx.y;
  gemm_body<1>(act + (size_t)b*CB*HW, W, g*96, bias, g*96,
               out + (size_t)b*4*CB*HW, g*96, 96, nullptr);
}

__global__ void __launch_bounds__(256,2) k_gemm_m2(
    const float* __restrict__ act, const float* __restrict__ W,
    const float* __restrict__ bias, float* __restrict__ out,
    const float* __restrict__ resid)
{
  int b = blockIdx.z;
  gemm_body<2>(act + (size_t)b*4*CB*HW, W, 0, bias, 0,
               out + (size_t)b*CB*HW, 0, 384, resid + (size_t)b*CB*HW);
}

// ---------------- proj GEMM: pixel-major act, epilogue x + a*rescale + rebias ----------------
__global__ void __launch_bounds__(256,2) k_gemm_proj(
    const float* __restrict__ actPM,
    const float* __restrict__ W, const float* __restrict__ bias,
    const float* __restrict__ xin, float* __restrict__ out)
{
  extern __shared__ float smem[];
  float* sA  = smem;             // [96 c][132 pitch]
  float* sWt = smem + 96*132;    // [96 c][100 pitch]
  const int tid=threadIdx.x, tx=tid&31, ty=tid>>5;
  const int b = blockIdx.z, px0 = blockIdx.x*128;
  const float* src = actPM + ((size_t)b*HW + px0)*96;
  #pragma unroll
  for (int j=0;j<12;j++){
    int i4 = tid + 256*j;
    float4 v = ((const float4*)src)[i4];
    int f = i4*4; int px = f/96; int c0 = f - px*96;
    sA[(c0+0)*132+px]=v.x; sA[(c0+1)*132+px]=v.y;
    sA[(c0+2)*132+px]=v.z; sA[(c0+3)*132+px]=v.w;
  }
  #pragma unroll
  for (int j=0;j<36;j++){
    int i = tid + 256*j;
    int r = i/96, cc = i - r*96;
    sWt[cc*100 + r] = W[(size_t)r*96 + cc];
  }
  __syncthreads();
  unsigned long long acc[6][4];
  #pragma unroll
  for (int p=0;p<6;p++){ acc[p][0]=0ull; acc[p][1]=0ull; acc[p][2]=0ull; acc[p][3]=0ull; }
  #pragma unroll 8
  for (int c=0;c<96;c++){
    float4 a = *(const float4*)(sA + c*132 + tx*4);
    unsigned long long a0=pack2(a.x), a1=pack2(a.y), a2=pack2(a.z), a3=pack2(a.w);
    const ulonglong2* wp = (const ulonglong2*)(sWt + c*100 + ty*12);
    ulonglong2 wA = wp[0], wB = wp[1], wC = wp[2];
    unsigned long long w[6] = {wA.x, wA.y, wB.x, wB.y, wC.x, wC.y};
    #pragma unroll
    for (int p=0;p<6;p++){
      ffma2(acc[p][0], w[p], a0);
      ffma2(acc[p][1], w[p], a1);
      ffma2(acc[p][2], w[p], a2);
      ffma2(acc[p][3], w[p], a3);
    }
  }
  #pragma unroll
  for (int p=0;p<6;p++){
    int o0 = ty*12 + 2*p, o1 = o0 + 1;
    float b0 = bias[o0], b1 = bias[o1];
    float rs0 = g_rescale[b][o0], rb0 = g_rebias[b][o0];
    float rs1 = g_rescale[b][o1], rb1 = g_rebias[b][o1];
    float2 r0=u2f(acc[p][0]), r1=u2f(acc[p][1]), r2=u2f(acc[p][2]), r3=u2f(acc[p][3]);
    size_t off0 = ((size_t)b*CB + o0)*HW + px0 + tx*4;
    size_t off1 = ((size_t)b*CB + o1)*HW + px0 + tx*4;
    float4 x0v = *(const float4*)(xin + off0);
    float4 x1v = *(const float4*)(xin + off1);
    float4 v0 = make_float4(x0v.x+(r0.x+b0)*rs0+rb0, x0v.y+(r1.x+b0)*rs0+rb0,
                            x0v.z+(r2.x+b0)*rs0+rb0, x0v.w+(r3.x+b0)*rs0+rb0);
    float4 v1 = make_float4(x1v.x+(r0.y+b1)*rs1+rb1, x1v.y+(r1.y+b1)*rs1+rb1,
                            x1v.z+(r2.y+b1)*rs1+rb1, x1v.w+(r3.y+b1)*rs1+rb1);
    *(float4*)(out + off0) = v0;
    *(float4*)(out + off1) = v1;
  }
}

// ---------------- attention: one (window, head) per 64-thread block, f32x2 ----------------
__global__ void __launch_bounds__(64) k_attn(const float* __restrict__ lsp){
  __shared__ __align__(16) float sK[32][64];
  __shared__ __align__(16) float sVt[64][36];
  int widx=blockIdx.x, h=blockIdx.y;
  int b=widx>>10, rem=widx&1023;
  int r0=(rem>>5)*8, c0=(rem&31)*8;
  int t=threadIdx.x;
  float ls = __expf(fminf(lsp[0], LOGIT_MAXV));
  size_t baseK = ((size_t)b*3*CB +   CB + h*32)*HW;
  size_t baseV = ((size_t)b*3*CB + 2*CB + h*32)*HW;
  for (int i=t;i<2048;i+=64){
    int d=i>>6, m=i&63;
    int hw = (r0+(m>>3))*256 + c0 + (m&7);
    sK[d][m]  = g_qkv[baseK + (size_t)d*HW + hw]*SCALEV;
    sVt[m][d] = g_qkv[baseV + (size_t)d*HW + hw];
  }
  int hw_t = (r0+(t>>3))*256 + c0 + (t&7);
  size_t baseQ = ((size_t)b*CB + h*32)*HW;
  unsigned long long q2[32];
  #pragma unroll
  for (int d=0;d<32;d++) q2[d] = pack2(g_co[baseQ + (size_t)d*HW + hw_t]);
  __syncthreads();
  float l[64];
  const float* brow = &g_bias_tab[h][t][0];
  #pragma unroll
  for (int m0=0;m0<64;m0+=4){
    unsigned long long s01=0ull, s23=0ull;
    #pragma unroll
    for (int d=0;d<32;d++){
      ulonglong2 kk = *(const ulonglong2*)&sK[d][m0];
      ffma2(s01, q2[d], kk.x);
      ffma2(s23, q2[d], kk.y);
    }
    float2 pa=u2f(s01), pb=u2f(s23);
    float4 bi = *(const float4*)(brow + m0);
    l[m0  ]=pa.x*ls+bi.x; l[m0+1]=pa.y*ls+bi.y;
    l[m0+2]=pb.x*ls+bi.z; l[m0+3]=pb.y*ls+bi.w;
  }
  float mx=l[0];
  #pragma unroll
  for (int m=1;m<64;m++) mx = fmaxf(mx,l[m]);
  float sum=0.f;
  #pragma unroll
  for (int m=0;m<64;m++){ float e=__expf(l[m]-mx); l[m]=e; sum+=e; }
  float inv = 1.f/sum;
  unsigned long long o2[16];
  #pragma unroll
  for (int i=0;i<16;i++) o2[i]=0ull;
  #pragma unroll
  for (int m=0;m<64;m++){
    unsigned long long p2 = pack2(l[m]);
    const ulonglong2* vp = (const ulonglong2*)&sVt[m][0];
    #pragma unroll
    for (int dd=0;dd<8;dd++){
      ulonglong2 vv = vp[dd];
      ffma2(o2[2*dd  ], p2, vv.x);
      ffma2(o2[2*dd+1], p2, vv.y);
    }
  }
  float* dst = g_attn + ((size_t)b*HW + hw_t)*96 + h*32;
  #pragma unroll
  for (int k=0;k<8;k++){
    float2 pa=u2f(o2[2*k]), pb=u2f(o2[2*k+1]);
    *(float4*)(dst + 4*k) = make_float4(pa.x*inv, pa.y*inv, pb.x*inv, pb.y*inv);
  }
}

// ---------------- host launch ----------------
extern "C" void kernel_launch(void* const* d_in, const int* in_sizes, int n_in,
                              void* d_out, int out_size){
  const float* x       = (const float*)d_in[0];
  const float* agn_w   = (const float*)d_in[1];
  const float* agn_b   = (const float*)d_in[2];
  const float* meta1_w = (const float*)d_in[3];
  const float* meta1_b = (const float*)d_in[4];
  const float* meta2_w = (const float*)d_in[5];
  const float* meta2_b = (const float*)d_in[6];
  const float* la1_w   = (const float*)d_in[7];
  const float* la1_b   = (const float*)d_in[8];
  const float* la2_w   = (const float*)d_in[9];
  const float* la2_b   = (const float*)d_in[10];
  const float* ta1_w   = (const float*)d_in[11];
  const float* ta1_b   = (const float*)d_in[12];
  const float* ta2_w   = (const float*)d_in[13];
  const float* ta2_b   = (const float*)d_in[14];
  const float* q_w     = (const float*)d_in[15];
  const float* q_b     = (const float*)d_in[16];
  const float* kv_w    = (const float*)d_in[17];
  const float* kv_b    = (const float*)d_in[18];
  const float* dw_w    = (const float*)d_in[19];
  const float* dw_b    = (const float*)d_in[20];
  const float* proj_w  = (const float*)d_in[21];
  const float* proj_b  = (const float*)d_in[22];
  const float* logit_s = (const float*)d_in[23];
  const float* rp_w1   = (const float*)d_in[24];
  const float* rp_b1   = (const float*)d_in[25];
  const float* rp_w2   = (const float*)d_in[26];
  const float* rp_b2   = (const float*)d_in[27];
  const float* m1_w    = (const float*)d_in[28];
  const float* m1_b    = (const float*)d_in[29];
  const float* m2_w    = (const float*)d_in[30];
  const float* m2_b    = (const float*)d_in[31];
  float* out = (float*)d_out;

  const int SM_CM = (96*128 + 96*100)*4;   // 87552
  const int SM_PM = (96*132 + 96*100)*4;   // 89088
  cudaFuncSetAttribute(k_gemm_qkv, cudaFuncAttributeMaxDynamicSharedMemorySize, SM_CM);
  cudaFuncSetAttribute(k_gemm_m1,  cudaFuncAttributeMaxDynamicSharedMemorySize, SM_CM);
  cudaFuncSetAttribute(k_gemm_m2,  cudaFuncAttributeMaxDynamicSharedMemorySize, SM_CM);
  cudaFuncSetAttribute(k_gemm_proj,cudaFuncAttributeMaxDynamicSharedMemorySize, SM_PM);

  float *p_y, *p_qkv, *p_attn, *p_x2, *p_hid;
  cudaGetSymbolAddress((void**)&p_y,    g_y);
  cudaGetSymbolAddress((void**)&p_qkv,  g_qkv);
  cudaGetSymbolAddress((void**)&p_attn, g_attn);
  cudaGetSymbolAddress((void**)&p_x2,   g_x2);
  cudaGetSymbolAddress((void**)&p_hid,  g_hid);

  // 1. stats + bias table
  k_reduce_partial<<<dim3(192,BATCH), 256>>>(x);
  k_finalize<<<BATCH, 256>>>(meta1_w, meta1_b, meta2_w, meta2_b);
  k_bias<<<64, 64>>>(rp_w1, rp_b1, rp_w2, rp_b2);

  // 2. fused AGN
  dim3 cgrid(IMG/32, IMG/8, BATCH*CB), cblk(32, 8);
  k_agn_fused<<<cgrid, cblk>>>(x, agn_w, agn_b, la1_w, la1_b, la2_w, la2_b,
                               ta1_w, ta1_b, ta2_w, ta2_b);

  // 3. QKV projections (single launch)
  k_gemm_qkv<<<dim3(512,3,BATCH), 256, SM_CM>>>(p_y, q_w, q_b, kv_w, kv_b, p_qkv);

  // 4. reflect 5x5 dwconv on Q, then window attention
  k_co5<<<cgrid, cblk>>>(dw_w, dw_b);
  k_attn<<<dim3(4096,3), 64>>>(logit_s);

  // 5. proj + residual/rescale/rebias
  k_gemm_proj<<<dim3(512,1,BATCH), 256, SM_PM>>>(p_attn, proj_w, proj_b, x, p_x2);

  // 6. MLP
  k_gemm_m1<<<dim3(512,4,BATCH), 256, SM_CM>>>(p_x2, m1_w, m1_b, p_hid);
  k_gemm_m2<<<dim3(512,1,BATCH), 256, SM_CM>>>(p_hid, m2_w, m2_b, out, p_x2);
}

// round 4
// speedup vs baseline: 2.0083x; 1.7405x over previous
#include <cuda_runtime.h>
#include <cuda_bf16.h>
#include <math.h>

#define HW 65536
#define IMG 256
#define CB 96
#define BATCH 4

// ---------------- device scratch ----------------
__device__ float g_mean[BATCH], g_istd[BATCH];
__device__ float g_rescale[BATCH][CB], g_rebias[BATCH][CB];
__device__ float g_partial[BATCH][192][2];
__device__ float g_bias_tab[3][64][64];

__device__ __nv_bfloat16 g_y  [(size_t)BATCH*CB*HW];      // AGN out (GEMM input only)
__device__ float         g_qkv[(size_t)BATCH*3*CB*HW];    // fp32 (attention consumes)
__device__ float         g_co [(size_t)BATCH*CB*HW];
__device__ __nv_bfloat16 g_attn[(size_t)BATCH*HW*CB];     // pixel-major bf16 (proj input)
__device__ float         g_x2 [(size_t)BATCH*CB*HW];      // fp32 (residual precision)
__device__ __nv_bfloat16 g_hid[(size_t)BATCH*4*CB*HW];    // bf16 (MLP2 input only)

#define SCALEV 0.17677669529663687f
#define LOGIT_MAXV 4.605170185988091f

// ---------------- f32x2 helpers (attention) ----------------
__device__ __forceinline__ unsigned long long pack2(float w){
  unsigned long long r; asm("mov.b64 %0, {%1, %1};" : "=l"(r) : "f"(w)); return r;
}
__device__ __forceinline__ float2 u2f(unsigned long long v){
  float2 f; asm("mov.b64 {%0, %1}, %2;" : "=f"(f.x), "=f"(f.y) : "l"(v)); return f;
}
__device__ __forceinline__ void ffma2(unsigned long long &d, unsigned long long a, unsigned long long b){
  asm("fma.rn.f32x2 %0, %1, %2, %0;" : "+l"(d) : "l"(a), "l"(b));
}

// ---------------- mma helpers ----------------
__device__ __forceinline__ void ldsm_x4(unsigned addr, unsigned &r0, unsigned &r1, unsigned &r2, unsigned &r3){
  asm volatile("ldmatrix.sync.aligned.m8n8.x4.shared.b16 {%0,%1,%2,%3}, [%4];"
    : "=r"(r0),"=r"(r1),"=r"(r2),"=r"(r3) : "r"(addr));
}
__device__ __forceinline__ void ldsm_x4_t(unsigned addr, unsigned &r0, unsigned &r1, unsigned &r2, unsigned &r3){
  asm volatile("ldmatrix.sync.aligned.m8n8.x4.trans.shared.b16 {%0,%1,%2,%3}, [%4];"
    : "=r"(r0),"=r"(r1),"=r"(r2),"=r"(r3) : "r"(addr));
}
__device__ __forceinline__ void ldsm_x2(unsigned addr, unsigned &r0, unsigned &r1){
  asm volatile("ldmatrix.sync.aligned.m8n8.x2.shared.b16 {%0,%1}, [%2];"
    : "=r"(r0),"=r"(r1) : "r"(addr));
}
__device__ __forceinline__ void mma16816(float* c, const unsigned* a, const unsigned* b){
  asm volatile("mma.sync.aligned.m16n8k16.row.col.f32.bf16.bf16.f32 "
    "{%0,%1,%2,%3},{%4,%5,%6,%7},{%8,%9},{%0,%1,%2,%3};"
    : "+f"(c[0]),"+f"(c[1]),"+f"(c[2]),"+f"(c[3])
    : "r"(a[0]),"r"(a[1]),"r"(a[2]),"r"(a[3]),"r"(b[0]),"r"(b[1]));
}
__device__ __forceinline__ unsigned bf2u(float x, float y){
  __nv_bfloat162 t = __floats2bfloat162_rn(x, y);
  return reinterpret_cast<unsigned&>(t);
}

// ---------------- K1: per-sample partial sums ----------------
__global__ void k_reduce_partial(const float* __restrict__ x){
  int b = blockIdx.y, blk = blockIdx.x, tid = threadIdx.x;
  const float4* xb = (const float4*)(x + (size_t)b*CB*HW);
  size_t base = (size_t)blk*8192;
  float s=0.f, s2=0.f;
  for (int i=tid;i<8192;i+=256){
    float4 v = xb[base+i];
    s  += v.x+v.y+v.z+v.w;
    s2 += v.x*v.x+v.y*v.y+v.z*v.z+v.w*v.w;
  }
  __shared__ float rs[256], rq[256];
  rs[tid]=s; rq[tid]=s2; __syncthreads();
  for (int st=128;st>0;st>>=1){
    if (tid<st){ rs[tid]+=rs[tid+st]; rq[tid]+=rq[tid+st]; }
    __syncthreads();
  }
  if (tid==0){ g_partial[b][blk][0]=rs[0]; g_partial[b][blk][1]=rq[0]; }
}

// ---------------- K2: finalize ----------------
__global__ void k_finalize(const float* __restrict__ m1w, const float* __restrict__ m1b,
                           const float* __restrict__ m2w, const float* __restrict__ m2b){
  int b = blockIdx.x, tid = threadIdx.x;
  __shared__ float rs[256], rq[256];
  rs[tid] = (tid<192)? g_partial[b][tid][0] : 0.f;
  rq[tid] = (tid<192)? g_partial[b][tid][1] : 0.f;
  __syncthreads();
  for (int st=128;st>0;st>>=1){
    if (tid<st){ rs[tid]+=rs[tid+st]; rq[tid]+=rq[tid+st]; }
    __syncthreads();
  }
  __shared__ float sh_mean, sh_std;
  if (tid==0){
    float M = (float)((size_t)CB*HW);
    float mean = rs[0]/M;
    float var  = rq[0]/M - mean*mean;
    float sd   = sqrtf(var + 1e-5f);
    g_mean[b]=mean; g_istd[b]=1.f/sd;
    sh_mean=mean; sh_std=sd;
  }
  __syncthreads();
  if (tid<CB){
    g_rescale[b][tid] = sh_std *m1w[tid] + m1b[tid];
    g_rebias [b][tid] = sh_mean*m2w[tid] + m2b[tid];
  }
}

// ---------------- K3: relative-position bias table ----------------
__global__ void k_bias(const float* __restrict__ w1, const float* __restrict__ b1,
                       const float* __restrict__ w2, const float* __restrict__ b2){
  int n = blockIdx.x, m = threadIdx.x;
  float di = (float)((n>>3) - (m>>3));
  float dj = (float)((n&7) - (m&7));
  float a0l = log1pf(fabsf(di)); float r0 = di<0.f ? -a0l : (di>0.f ? a0l : 0.f);
  float a1l = log1pf(fabsf(dj)); float r1 = dj<0.f ? -a1l : (dj>0.f ? a1l : 0.f);
  float a0=0.f,a1=0.f,a2=0.f;
  for (int k=0;k<256;k++){
    float h = fmaxf(r0*w1[2*k]+r1*w1[2*k+1]+b1[k], 0.f);
    a0 += h*w2[k]; a1 += h*w2[256+k]; a2 += h*w2[512+k];
  }
  g_bias_tab[0][n][m]=a0+b2[0];
  g_bias_tab[1][n][m]=a1+b2[1];
  g_bias_tab[2][n][m]=a2+b2[2];
}

// ---------------- K4: fused AGN ----------------
__global__ void k_agn_fused(const float* __restrict__ x,
    const float* __restrict__ agnw, const float* __restrict__ agnb,
    const float* __restrict__ la1w, const float* __restrict__ la1b,
    const float* __restrict__ la2w, const float* __restrict__ la2b,
    const float* __restrict__ ta1w, const float* __restrict__ ta1b,
    const float* __restrict__ ta2w, const float* __restrict__ ta2b){
  int bc = blockIdx.z; int b = bc/CB, c = bc - b*CB;
  const float* xb = x + (size_t)bc*HW;
  float mean = g_mean[b], istd = g_istd[b];
  __shared__ float xt[12][36];
  __shared__ __align__(8) float2 tb[10][36];
  int x0 = blockIdx.x*32, y0 = blockIdx.y*8;
  int tid = threadIdx.y*32 + threadIdx.x;
  for (int i=tid; i<432; i+=256){
    int ry = i/36, rx = i-ry*36;
    int gy = y0+ry-2, gx = x0+rx-2;
    float v = 0.f;
    if ((unsigned)gy<256u && (unsigned)gx<256u) v = (xb[gy*256+gx]-mean)*istd;
    xt[ry][rx] = v;
  }
  float w1l[9], w1t[9], w2l[9], w2t[9];
  #pragma unroll
  for (int k=0;k<9;k++){
    w1l[k]=la1w[c*9+k]; w1t[k]=ta1w[c*9+k];
    w2l[k]=la2w[c*9+k]; w2t[k]=ta2w[c*9+k];
  }
  float b1l=la1b[c], b1t=ta1b[c];
  __syncthreads();
  for (int i=tid; i<340; i+=256){
    int ry = i/34, rx = i-ry*34;
    int gy = y0+ry-1, gx = x0+rx-1;
    float al=b1l, at=b1t;
    #pragma unroll
    for (int ky=0;ky<3;ky++)
      #pragma unroll
      for (int kx=0;kx<3;kx++){
        float v = xt[ry+ky][rx+kx];
        al += v*w1l[ky*3+kx]; at += v*w1t[ky*3+kx];
      }
    bool in = (unsigned)gy<256u && (unsigned)gx<256u;
    tb[ry][rx] = in ? make_float2(fmaxf(al,0.f), fmaxf(at,0.f)) : make_float2(0.f,0.f);
  }
  __syncthreads();
  int ty=threadIdx.y, tx=threadIdx.x;
  float acc = la2b[c] + ta2b[c];
  #pragma unroll
  for (int ky=0;ky<3;ky++)
    #pragma unroll
    for (int kx=0;kx<3;kx++){
      float2 v = tb[ty+ky][tx+kx];
      acc += v.x*w2l[ky*3+kx] + v.y*w2t[ky*3+kx];
    }
  float xn = xt[ty+2][tx+2];
  size_t o = (size_t)bc*HW + (size_t)(y0+ty)*256 + x0+tx;
  float r = xn*(agnw[c]*g_rescale[b][c]) + (agnb[c]+g_rebias[b][c]) + acc;
  g_y[o] = __float2bfloat16(r);
}

// ---------------- K6: 5x5 reflect-padded dwconv on Q ----------------
__global__ void k_co5(const float* __restrict__ dww, const float* __restrict__ dwb){
  int bc=blockIdx.z; int b=bc/CB, c=bc-b*CB;
  const float* Q = g_qkv + ((size_t)b*3*CB + c)*HW;
  __shared__ float tile[12][36];
  int x0=blockIdx.x*32, y0=blockIdx.y*8;
  int tid=threadIdx.y*32+threadIdx.x;
  for (int i=tid;i<432;i+=256){
    int ry=i/36, rx=i-ry*36;
    int gy=y0+ry-2, gx=x0+rx-2;
    gy = gy<0 ? -gy : (gy>255 ? 510-gy : gy);
    gx = gx<0 ? -gx : (gx>255 ? 510-gx : gx);
    tile[ry][rx] = Q[gy*256+gx];
  }
  __syncthreads();
  float w[25];
  #pragma unroll
  for (int k=0;k<25;k++) w[k]=dww[c*25+k];
  float acc = dwb[c];
  #pragma unroll
  for (int ky=0;ky<5;ky++)
    #pragma unroll
    for (int kx=0;kx<5;kx++)
      acc += tile[threadIdx.y+ky][threadIdx.x+kx]*w[ky*5+kx];
  g_co[(size_t)bc*HW + (size_t)(y0+threadIdx.y)*256 + x0+threadIdx.x] = acc;
}

// =====================================================================
// Tensor-core GEMM: block tile 128px(M) x 96out(N), K chunks of 96.
// LOAD: 0 = channel-major fp32, 1 = channel-major bf16, 2 = pixel-major bf16
// EPI:  0 = bias (fp32 out), 1 = bias+relu (bf16 out), 2 = bias+resid (fp32),
//       3 = xin + (v+bias)*rescale + rebias (fp32)
// smem: A tile (swizzled [k][px] for CM, [px][k+pad] for PM) + W [n][k+pad];
//       overlaid fp32 stage buffer [96][132] for the epilogue.
// =====================================================================
#define SMEM_MMA 50688

template<int LOAD, int EPI>
__device__ __forceinline__ void mma_body(
    const void* actb, const float* W, const float* bias,
    int CinTot, int wrow0, void* outv,
    const float* xinb, int bIdx)
{
  extern __shared__ char smem_raw[];
  __nv_bfloat16* sA = (__nv_bfloat16*)smem_raw;
  __nv_bfloat16* sW = (__nv_bfloat16*)(smem_raw + (LOAD==2 ? 26624 : 24576));
  float* sStage = (float*)smem_raw;
  const int tid = threadIdx.x;
  const int px0 = blockIdx.x * 128;
  const int warp = tid >> 5, t = tid & 31;
  const int m0w = (warp>>1)*32, n0w = (warp&1)*48;
  unsigned sAb = (unsigned)__cvta_generic_to_shared(sA);
  unsigned sWb = (unsigned)__cvta_generic_to_shared(sW);

  float acc[2][6][4];
  #pragma unroll
  for (int mi=0;mi<2;mi++)
    #pragma unroll
    for (int nj=0;nj<6;nj++)
      #pragma unroll
      for (int e=0;e<4;e++) acc[mi][nj][e]=0.f;

  // lane geometry for ldmatrix
  const int g = t>>3, gi = t&7;
  const int t15 = t&15;

  for (int k0g=0; k0g<CinTot; k0g+=96){
    // ---- load A chunk ----
    if (LOAD==0){
      const float* a = (const float*)actb;
      #pragma unroll
      for (int j=0;j<12;j++){
        int i = tid + 256*j;
        int c = i>>5, px = (i&31)*4;
        float4 v = *(const float4*)(a + (size_t)(k0g+c)*HW + px0 + px);
        uint2 u; u.x = bf2u(v.x,v.y); u.y = bf2u(v.z,v.w);
        *(uint2*)(sA + c*128 + ((((px>>3)^(c&7))<<3) + (px&7))) = u;
      }
    } else if (LOAD==1){
      const __nv_bfloat16* a = (const __nv_bfloat16*)actb;
      #pragma unroll
      for (int j=0;j<6;j++){
        int i = tid + 256*j;
        int c = i>>4, s8 = (i&15)*8;
        uint4 v = *(const uint4*)(a + (size_t)(k0g+c)*HW + px0 + s8);
        *(uint4*)(sA + c*128 + ((((s8>>3)^(c&7))<<3))) = v;
      }
    } else {
      const __nv_bfloat16* a = (const __nv_bfloat16*)actb + (size_t)px0*96;
      #pragma unroll
      for (int j=0;j<6;j++){
        int i = tid + 256*j;
        int px = i/12, c0 = (i%12)*8;
        uint4 v = *(const uint4*)(a + (size_t)px*96 + c0);
        *(uint4*)(sA + px*104 + c0) = v;
      }
    }
    // ---- load W chunk ----
    #pragma unroll
    for (int j=0;j<9;j++){
      int i = tid + 256*j;
      int r = i/24, c4 = (i%24)*4;
      float4 v = *(const float4*)(W + (size_t)(wrow0+r)*CinTot + k0g + c4);
      uint2 u; u.x = bf2u(v.x,v.y); u.y = bf2u(v.z,v.w);
      *(uint2*)(sW + r*104 + c4) = u;
    }
    __syncthreads();

    // ---- lane base addresses ----
    unsigned addrA[2], addrB[6];
    if (LOAD==2){
      int row0 = m0w + (g&1)*8 + gi;
      int kc = (g>=2)?16:0;
      addrA[0] = sAb + (row0     )*208 + kc;
      addrA[1] = sAb + (row0 + 16)*208 + kc;
    } else {
      int kb = ((g>=2)?8:0) + gi;
      int px_a0 = m0w + (g&1)*8;
      int px_a1 = px_a0 + 16;
      addrA[0] = sAb + kb*256 + ((((px_a0>>3) ^ gi)<<4));
      addrA[1] = sAb + kb*256 + ((((px_a1>>3) ^ gi)<<4));
    }
    {
      int n = n0w + (t15&7);
      int kc = (t15>>3)*8;
      #pragma unroll
      for (int nj=0;nj<6;nj++) addrB[nj] = sWb + (n + nj*8)*208 + kc*2;
    }

    #pragma unroll
    for (int ks=0; ks<6; ks++){
      unsigned a[2][4], bfr[6][2];
      if (LOAD==2){ ldsm_x4(addrA[0], a[0][0],a[0][1],a[0][2],a[0][3]);
                    ldsm_x4(addrA[1], a[1][0],a[1][1],a[1][2],a[1][3]); }
      else        { ldsm_x4_t(addrA[0], a[0][0],a[0][1],a[0][2],a[0][3]);
                    ldsm_x4_t(addrA[1], a[1][0],a[1][1],a[1][2],a[1][3]); }
      #pragma unroll
      for (int nj=0;nj<6;nj++) ldsm_x2(addrB[nj], bfr[nj][0], bfr[nj][1]);
      #pragma unroll
      for (int mi=0;mi<2;mi++)
        #pragma unroll
        for (int nj=0;nj<6;nj++)
          mma16816(acc[mi][nj], a[mi], bfr[nj]);
      if (LOAD==2){ addrA[0]+=32; addrA[1]+=32; }
      else        { addrA[0]+=4096; addrA[1]+=4096; }
      #pragma unroll
      for (int nj=0;nj<6;nj++) addrB[nj]+=32;
    }
    __syncthreads();
  }

  // ---- stage accumulators to smem ----
  #pragma unroll
  for (int mi=0;mi<2;mi++)
    #pragma unroll
    for (int nj=0;nj<6;nj++){
      int m = m0w + mi*16 + (t>>2);
      int n = n0w + nj*8 + (t&3)*2;
      sStage[(n  )*132 + m  ] = acc[mi][nj][0];
      sStage[(n+1)*132 + m  ] = acc[mi][nj][1];
      sStage[(n  )*132 + m+8] = acc[mi][nj][2];
      sStage[(n+1)*132 + m+8] = acc[mi][nj][3];
    }
  __syncthreads();

  // ---- vectorized writeout ----
  const int tx = tid&31, ty = tid>>5;
  #pragma unroll
  for (int r=0;r<12;r++){
    int o = ty*12 + r;
    float4 v = *(float4*)(sStage + o*132 + tx*4);
    float bv = bias[wrow0+o];
    v.x+=bv; v.y+=bv; v.z+=bv; v.w+=bv;
    size_t off = (size_t)o*HW + px0 + tx*4;
    if (EPI==0){
      *(float4*)((float*)outv + off) = v;
    } else if (EPI==1){
      v.x=fmaxf(v.x,0.f); v.y=fmaxf(v.y,0.f); v.z=fmaxf(v.z,0.f); v.w=fmaxf(v.w,0.f);
      uint2 u; u.x = bf2u(v.x,v.y); u.y = bf2u(v.z,v.w);
      *(uint2*)((__nv_bfloat16*)outv + off) = u;
    } else if (EPI==2){
      float4 q = *(const float4*)(xinb + off);
      v.x+=q.x; v.y+=q.y; v.z+=q.z; v.w+=q.w;
      *(float4*)((float*)outv + off) = v;
    } else {
      float rs = g_rescale[bIdx][o], rb = g_rebias[bIdx][o];
      float4 xi = *(const float4*)(xinb + off);
      v = make_float4(xi.x + v.x*rs + rb, xi.y + v.y*rs + rb,
                      xi.z + v.z*rs + rb, xi.w + v.w*rs + rb);
      *(float4*)((float*)outv + off) = v;
    }
  }
}

__global__ void __launch_bounds__(256) k_mma_qkv(
    const float* __restrict__ qW, const float* __restrict__ qb,
    const float* __restrict__ kvW, const float* __restrict__ kvb)
{
  int b = blockIdx.z, gy = blockIdx.y;
  const __nv_bfloat16* actb = g_y + (size_t)b*CB*HW;
  float* outb = g_qkv + ((size_t)b*3*CB + gy*96)*HW;
  if (gy==0) mma_body<1,0>(actb, qW, qb, 96, 0, outb, nullptr, b);
  else       mma_body<1,0>(actb, kvW, kvb, 96, (gy-1)*96, outb, nullptr, b);
}

__global__ void __launch_bounds__(256) k_mma_proj(
    const float* __restrict__ W, const float* __restrict__ bias,
    const float* __restrict__ xin)
{
  int b = blockIdx.z;
  const __nv_bfloat16* actb = g_attn + (size_t)b*HW*96;
  mma_body<2,3>(actb, W, bias, 96, 0, g_x2 + (size_t)b*CB*HW,
                xin + (size_t)b*CB*HW, b);
}

__global__ void __launch_bounds__(256) k_mma_m1(
    const float* __restrict__ W, const float* __restrict__ bias)
{
  int b = blockIdx.z, gy = blockIdx.y;
  mma_body<0,1>(g_x2 + (size_t)b*CB*HW, W, bias, 96, gy*96,
                g_hid + ((size_t)b*4*CB + gy*96)*HW, nullptr, b);
}

__global__ void __launch_bounds__(256) k_mma_m2(
    const float* __restrict__ W, const float* __restrict__ bias,
    float* __restrict__ out)
{
  int b = blockIdx.z;
  mma_body<1,2>(g_hid + (size_t)b*4*CB*HW, W, bias, 384, 0,
                out + (size_t)b*CB*HW, g_x2 + (size_t)b*CB*HW, b);
}

// ---------------- attention: one (window, head) per 64-thread block ----------------
__global__ void __launch_bounds__(64) k_attn(const float* __restrict__ lsp){
  __shared__ __align__(16) float sK[32][64];
  __shared__ __align__(16) float sVt[64][36];
  int widx=blockIdx.x, h=blockIdx.y;
  int b=widx>>10, rem=widx&1023;
  int r0=(rem>>5)*8, c0=(rem&31)*8;
  int t=threadIdx.x;
  float ls = __expf(fminf(lsp[0], LOGIT_MAXV));
  size_t baseK = ((size_t)b*3*CB +   CB + h*32)*HW;
  size_t baseV = ((size_t)b*3*CB + 2*CB + h*32)*HW;
  for (int i=t;i<2048;i+=64){
    int d=i>>6, m=i&63;
    int hw = (r0+(m>>3))*256 + c0 + (m&7);
    sK[d][m]  = g_qkv[baseK + (size_t)d*HW + hw]*SCALEV;
    sVt[m][d] = g_qkv[baseV + (size_t)d*HW + hw];
  }
  int hw_t = (r0+(t>>3))*256 + c0 + (t&7);
  size_t baseQ = ((size_t)b*CB + h*32)*HW;
  unsigned long long q2[32];
  #pragma unroll
  for (int d=0;d<32;d++) q2[d] = pack2(g_co[baseQ + (size_t)d*HW + hw_t]);
  __syncthreads();
  float l[64];
  const float* brow = &g_bias_tab[h][t][0];
  #pragma unroll
  for (int m0=0;m0<64;m0+=4){
    unsigned long long s01=0ull, s23=0ull;
    #pragma unroll
    for (int d=0;d<32;d++){
      ulonglong2 kk = *(const ulonglong2*)&sK[d][m0];
      ffma2(s01, q2[d], kk.x);
      ffma2(s23, q2[d], kk.y);
    }
    float2 pa=u2f(s01), pb=u2f(s23);
    float4 bi = *(const float4*)(brow + m0);
    l[m0  ]=pa.x*ls+bi.x; l[m0+1]=pa.y*ls+bi.y;
    l[m0+2]=pb.x*ls+bi.z; l[m0+3]=pb.y*ls+bi.w;
  }
  float mx=l[0];
  #pragma unroll
  for (int m=1;m<64;m++) mx = fmaxf(mx,l[m]);
  float sum=0.f;
  #pragma unroll
  for (int m=0;m<64;m++){ float e=__expf(l[m]-mx); l[m]=e; sum+=e; }
  float inv = 1.f/sum;
  unsigned long long o2[16];
  #pragma unroll
  for (int i=0;i<16;i++) o2[i]=0ull;
  #pragma unroll
  for (int m=0;m<64;m++){
    unsigned long long p2 = pack2(l[m]);
    const ulonglong2* vp = (const ulonglong2*)&sVt[m][0];
    #pragma unroll
    for (int dd=0;dd<8;dd++){
      ulonglong2 vv = vp[dd];
      ffma2(o2[2*dd  ], p2, vv.x);
      ffma2(o2[2*dd+1], p2, vv.y);
    }
  }
  __nv_bfloat16* dst = g_attn + ((size_t)b*HW + hw_t)*96 + h*32;
  #pragma unroll
  for (int k=0;k<8;k++){
    float2 pa=u2f(o2[2*k]), pb=u2f(o2[2*k+1]);
    uint2 u; u.x = bf2u(pa.x*inv, pa.y*inv); u.y = bf2u(pb.x*inv, pb.y*inv);
    *(uint2*)(dst + 4*k) = u;
  }
}

// ---------------- host launch ----------------
extern "C" void kernel_launch(void* const* d_in, const int* in_sizes, int n_in,
                              void* d_out, int out_size){
  const float* x       = (const float*)d_in[0];
  const float* agn_w   = (const float*)d_in[1];
  const float* agn_b   = (const float*)d_in[2];
  const float* meta1_w = (const float*)d_in[3];
  const float* meta1_b = (const float*)d_in[4];
  const float* meta2_w = (const float*)d_in[5];
  const float* meta2_b = (const float*)d_in[6];
  const float* la1_w   = (const float*)d_in[7];
  const float* la1_b   = (const float*)d_in[8];
  const float* la2_w   = (const float*)d_in[9];
  const float* la2_b   = (const float*)d_in[10];
  const float* ta1_w   = (const float*)d_in[11];
  const float* ta1_b   = (const float*)d_in[12];
  const float* ta2_w   = (const float*)d_in[13];
  const float* ta2_b   = (const float*)d_in[14];
  const float* q_w     = (const float*)d_in[15];
  const float* q_b     = (const float*)d_in[16];
  const float* kv_w    = (const float*)d_in[17];
  const float* kv_b    = (const float*)d_in[18];
  const float* dw_w    = (const float*)d_in[19];
  const float* dw_b    = (const float*)d_in[20];
  const float* proj_w  = (const float*)d_in[21];
  const float* proj_b  = (const float*)d_in[22];
  const float* logit_s = (const float*)d_in[23];
  const float* rp_w1   = (const float*)d_in[24];
  const float* rp_b1   = (const float*)d_in[25];
  const float* rp_w2   = (const float*)d_in[26];
  const float* rp_b2   = (const float*)d_in[27];
  const float* m1_w    = (const float*)d_in[28];
  const float* m1_b    = (const float*)d_in[29];
  const float* m2_w    = (const float*)d_in[30];
  const float* m2_b    = (const float*)d_in[31];
  float* out = (float*)d_out;

  cudaFuncSetAttribute(k_mma_qkv, cudaFuncAttributeMaxDynamicSharedMemorySize, SMEM_MMA);
  cudaFuncSetAttribute(k_mma_proj,cudaFuncAttributeMaxDynamicSharedMemorySize, SMEM_MMA);
  cudaFuncSetAttribute(k_mma_m1,  cudaFuncAttributeMaxDynamicSharedMemorySize, SMEM_MMA);
  cudaFuncSetAttribute(k_mma_m2,  cudaFuncAttributeMaxDynamicSharedMemorySize, SMEM_MMA);

  // 1. stats + bias table
  k_reduce_partial<<<dim3(192,BATCH), 256>>>(x);
  k_finalize<<<BATCH, 256>>>(meta1_w, meta1_b, meta2_w, meta2_b);
  k_bias<<<64, 64>>>(rp_w1, rp_b1, rp_w2, rp_b2);

  // 2. fused AGN (writes bf16 g_y)
  dim3 cgrid(IMG/32, IMG/8, BATCH*CB), cblk(32, 8);
  k_agn_fused<<<cgrid, cblk>>>(x, agn_w, agn_b, la1_w, la1_b, la2_w, la2_b,
                               ta1_w, ta1_b, ta2_w, ta2_b);

  // 3. QKV projections (tensor cores)
  k_mma_qkv<<<dim3(512,3,BATCH), 256, SMEM_MMA>>>(q_w, q_b, kv_w, kv_b);

  // 4. reflect 5x5 dwconv on Q, then window attention (writes bf16 g_attn)
  k_co5<<<cgrid, cblk>>>(dw_w, dw_b);
  k_attn<<<dim3(4096,3), 64>>>(logit_s);

  // 5. proj + residual/rescale/rebias -> g_x2 (fp32)
  k_mma_proj<<<dim3(512,1,BATCH), 256, SMEM_MMA>>>(proj_w, proj_b, x);

  // 6. MLP (m1 -> bf16 hid, m2 -> out fp32 with resid)
  k_mma_m1<<<dim3(512,4,BATCH), 256, SMEM_MMA>>>(m1_w, m1_b);
  k_mma_m2<<<dim3(512,1,BATCH), 256, SMEM_MMA>>>(m2_w, m2_b, out);
}